// round 2
// baseline (speedup 1.0000x reference)
#include <cuda_runtime.h>
#include <cstdint>
#include <math_constants.h>

// Sparsemax along last dim (d = 1024), one warp per row.
// Exact threshold via Michelot's algorithm warm-started at tau0 = max(z) - 1
// (valid: tau* >= max-1 since p_max <= 1, so support ⊆ {z > max-1}).
// The active set at tau0 is tiny for typical inputs, so we compact it to
// shared memory once and iterate only over the compacted values.

constexpr int D   = 1024;  // last-dim size
constexpr int WPB = 8;     // warps per block
constexpr int CAP = 1024;  // compaction capacity == D -> always sufficient

__global__ void __launch_bounds__(WPB * 32)
sparsemax_kernel(const float* __restrict__ z, float* __restrict__ p, int rows) {
    __shared__ float buf[WPB][CAP];

    const int wl   = threadIdx.x >> 5;
    const int lane = threadIdx.x & 31;
    const int warp_global = blockIdx.x * WPB + wl;
    if (warp_global >= rows) return;

    const float* zr = z + (size_t)warp_global * D;
    float*       pr = p + (size_t)warp_global * D;

    // ---- load row: 8 x float4 per lane, coalesced, streaming (single use) ----
    float v[32];
#pragma unroll
    for (int j = 0; j < 8; j++) {
        float4 t = __ldcs(reinterpret_cast<const float4*>(zr + j * 128 + lane * 4));
        v[4 * j + 0] = t.x;
        v[4 * j + 1] = t.y;
        v[4 * j + 2] = t.z;
        v[4 * j + 3] = t.w;
    }

    // ---- row max ----
    float m = v[0];
#pragma unroll
    for (int i = 1; i < 32; i++) m = fmaxf(m, v[i]);
#pragma unroll
    for (int o = 16; o > 0; o >>= 1)
        m = fmaxf(m, __shfl_xor_sync(0xffffffffu, m, o));

    float tau = m - 1.0f;

    // ---- compact active set {z > tau0} into shared (ballot prefix) ----
    const unsigned lt = (1u << lane) - 1u;
    int cnt = 0;
#pragma unroll
    for (int i = 0; i < 32; i++) {
        bool a = v[i] > tau;
        unsigned msk = __ballot_sync(0xffffffffu, a);
        if (a) buf[wl][cnt + __popc(msk & lt)] = v[i];
        cnt += __popc(msk);
    }
    __syncwarp();

    // ---- Michelot fixed-point iterations on the compacted set ----
    if (cnt <= 32) {
        // common case: one active value (or none) per lane, all in registers
        float x = (lane < cnt) ? buf[wl][lane] : -CUDART_INF_F;
#pragma unroll 1
        for (int it = 0; it < 40; it++) {
            bool a = x > tau;
            float s = a ? x : 0.0f;
            int k = __popc(__ballot_sync(0xffffffffu, a));   // k >= 1 always
#pragma unroll
            for (int o = 16; o > 0; o >>= 1)
                s += __shfl_xor_sync(0xffffffffu, s, o);
            float nt = (s - 1.0f) / (float)k;
            if (nt == tau) break;   // exact fixed point = sparsemax threshold
            tau = nt;
        }
    } else {
        // rare: walk the shared buffer (still only cnt elements, not D)
#pragma unroll 1
        for (int it = 0; it < 64; it++) {
            float s = 0.0f, k = 0.0f;
            for (int t = lane; t < cnt; t += 32) {
                float x = buf[wl][t];
                if (x > tau) { s += x; k += 1.0f; }
            }
#pragma unroll
            for (int o = 16; o > 0; o >>= 1) {
                s += __shfl_xor_sync(0xffffffffu, s, o);
                k += __shfl_xor_sync(0xffffffffu, k, o);
            }
            float nt = (s - 1.0f) / k;
            if (nt == tau) break;
            tau = nt;
        }
    }

    // ---- write p = relu(z - tau), coalesced float4 streaming stores ----
#pragma unroll
    for (int j = 0; j < 8; j++) {
        float4 t;
        t.x = fmaxf(v[4 * j + 0] - tau, 0.0f);
        t.y = fmaxf(v[4 * j + 1] - tau, 0.0f);
        t.z = fmaxf(v[4 * j + 2] - tau, 0.0f);
        t.w = fmaxf(v[4 * j + 3] - tau, 0.0f);
        __stcs(reinterpret_cast<float4*>(pr + j * 128 + lane * 4), t);
    }
}

extern "C" void kernel_launch(void* const* d_in, const int* in_sizes, int n_in,
                              void* d_out, int out_size) {
    const float* z = (const float*)d_in[0];
    float* p = (float*)d_out;
    const int rows = in_sizes[0] / D;                 // 32768
    const int grid = (rows + WPB - 1) / WPB;          // 4096
    sparsemax_kernel<<<grid, WPB * 32>>>(z, p, rows);
}